// round 12
// baseline (speedup 1.0000x reference)
#include <cuda_runtime.h>
#include <cuda_bf16.h>

#define BATCH 16384
#define FEAT 512
#define NCLS 100000
#define ALPHA 0.5f
#define LAMDA 0.003f

// Block layout of the mega kernel: fused blocks FIRST (their gather latency
// hides behind abundant co-resident copy work), copy blocks last (pure
// bandwidth keeps DRAM saturated through the tail waves).
#define FUSED_BLOCKS (BATCH / 2)                       // 8192 (2 samples/block)
#define COPY_CHUNKS  (NCLS * (FEAT / 4) / 4)           // 3,200,000 64B chunks
#define COPY_BLOCKS  ((COPY_CHUNKS + 255) / 256)       // 12500

// Scratch (allocation-free __device__ globals, zero-initialized at load).
// INVARIANT: g_counts is all-zero at kernel_launch entry. It is re-zeroed by
// dup_and_reset_kernel (the final launch) every call, so the invariant holds
// for the correctness run, the capture, and every graph replay alike.
__device__ int g_counts[NCLS];
__device__ int g_cnt_b[BATCH];      // per-sample class count, stashed by mega

__global__ void count_kernel(const int* __restrict__ targets) {
    int i = blockIdx.x * blockDim.x + threadIdx.x;
    if (i < BATCH) atomicAdd(&g_counts[targets[i]], 1);
}

// One grid doing both jobs so the DRAM pipe never drains:
//  - blocks [0, FUSED_BLOCKS): loss/tw + direct center rewrite (cnt==1)
//  - blocks [FUSED_BLOCKS, +COPY_BLOCKS): streaming copy of center rows,
//    skipping cnt==1 rows (owned by the fused half). cnt>1 rows ARE copied
//    (they are the accumulation base for dup_and_reset_kernel).
__global__ __launch_bounds__(256) void mega_kernel(
    const float4* __restrict__ inputs,
    const float4* __restrict__ centers,
    const float*  __restrict__ wpc,
    const int*    __restrict__ targets,
    float4* __restrict__ loss_out,
    float4* __restrict__ tw_out,
    float4* __restrict__ new_centers) {

    const int bid = blockIdx.x;

    if (bid < FUSED_BLOCKS) {
        // ---- fused half: 2 samples per block, 128 threads each ----
        const int group = threadIdx.x >> 7;         // 0..1
        const int d4    = threadIdx.x & 127;        // 0..127
        const int b = bid * 2 + group;

        const int t   = __ldg(&targets[b]);
        const int cnt = g_counts[t];
        const float w = LAMDA * __ldg(&wpc[t]);
        const float s = ALPHA / (1.0f + (float)cnt);

        if (d4 == 0) g_cnt_b[b] = cnt;   // stash for the dup pass

        const size_t ib = (size_t)b * (FEAT / 4) + d4;
        const size_t ic = (size_t)t * (FEAT / 4) + d4;
        const float4 x = inputs[ib];
        const float4 c = centers[ic];

        float4 l;
        float dx;
        dx = x.x - c.x; l.x = 0.5f * dx * dx;
        dx = x.y - c.y; l.y = 0.5f * dx * dx;
        dx = x.z - c.z; l.z = 0.5f * dx * dx;
        dx = x.w - c.w; l.w = 0.5f * dx * dx;

        loss_out[ib] = l;
        tw_out[ib]   = make_float4(w, w, w, w);

        if (cnt == 1) {
            // Sole sample of its class: full row rewrite, no atomics.
            new_centers[ic] = make_float4(c.x - s * x.x, c.y - s * x.y,
                                          c.z - s * x.z, c.w - s * x.w);
        }
        // cnt > 1: handled by dup_and_reset_kernel after the base row copy.
    } else {
        // ---- copy half: 64B (4 float4) per thread, one row per thread ----
        const int tchunk = (bid - FUSED_BLOCKS) * 256 + threadIdx.x;
        const size_t i = (size_t)tchunk * 4;        // float4 index
        const int row = (int)(i >> 7);              // 128 float4 per row
        if (row >= NCLS) return;
        if (g_counts[row] == 1) return;             // fused half owns it
        float4 v0 = __ldcs(&centers[i + 0]);
        float4 v1 = __ldcs(&centers[i + 1]);
        float4 v2 = __ldcs(&centers[i + 2]);
        float4 v3 = __ldcs(&centers[i + 3]);
        __stcs(&new_centers[i + 0], v0);
        __stcs(&new_centers[i + 1], v1);
        __stcs(&new_centers[i + 2], v2);
        __stcs(&new_centers[i + 3], v3);
    }
}

// Final pass, two jobs in one launch:
//  1) duplicate-class accumulation: scan all samples via the g_cnt_b stash
//     (NOT g_counts), accumulate -s*x onto the copied base rows (~1.6% of
//     samples -> ~0.7M near-conflict-free RED.F32).
//  2) re-zero g_counts for the next call (safe: nothing here reads it).
#define DUP_GRID 296
__global__ __launch_bounds__(128) void dup_and_reset_kernel(
    const float4* __restrict__ inputs,
    const int*    __restrict__ targets,
    float* __restrict__ new_centers) {

    const int d4 = threadIdx.x;

    for (int b = blockIdx.x; b < BATCH; b += DUP_GRID) {
        const int cnt = g_cnt_b[b];
        if (cnt <= 1) continue;
        const float s = ALPHA / (1.0f + (float)cnt);
        const int t = __ldg(&targets[b]);
        const float4 x = inputs[(size_t)b * (FEAT / 4) + d4];
        float* dst = new_centers + (size_t)t * FEAT + d4 * 4;
        atomicAdd(dst + 0, -s * x.x);
        atomicAdd(dst + 1, -s * x.y);
        atomicAdd(dst + 2, -s * x.z);
        atomicAdd(dst + 3, -s * x.w);
    }

    // Restore the all-zero invariant on g_counts (37,888 threads, 3 ints ea).
    const int tid = blockIdx.x * 128 + threadIdx.x;
    for (int i = tid; i < NCLS; i += DUP_GRID * 128) g_counts[i] = 0;
}

extern "C" void kernel_launch(void* const* d_in, const int* in_sizes, int n_in,
                              void* d_out, int out_size) {
    const float* inputs  = (const float*)d_in[0];   // [BATCH, FEAT]
    const float* centers = (const float*)d_in[1];   // [NCLS, FEAT]
    const float* wpc     = (const float*)d_in[2];   // [NCLS]
    const int*   targets = (const int*)d_in[3];     // [BATCH]

    float* out  = (float*)d_out;
    float* loss = out;                                  // [BATCH, FEAT]
    float* tw   = out + (size_t)BATCH * FEAT;           // [BATCH, FEAT]
    float* newc = out + (size_t)2 * BATCH * FEAT;       // [NCLS, FEAT]

    count_kernel<<<(BATCH + 255) / 256, 256>>>(targets);

    mega_kernel<<<FUSED_BLOCKS + COPY_BLOCKS, 256>>>(
        (const float4*)inputs, (const float4*)centers, wpc, targets,
        (float4*)loss, (float4*)tw, (float4*)newc);

    dup_and_reset_kernel<<<DUP_GRID, 128>>>(
        (const float4*)inputs, targets, newc);
}

// round 13
// speedup vs baseline: 1.0063x; 1.0063x over previous
#include <cuda_runtime.h>
#include <cuda_bf16.h>

#define BATCH 16384
#define FEAT 512
#define NCLS 100000
#define ALPHA 0.5f
#define LAMDA 0.003f

// Block layout of the mega kernel: fused blocks FIRST (their gather latency
// hides behind abundant co-resident copy work), copy blocks last (pure
// bandwidth keeps DRAM saturated through the tail waves).
#define FUSED_BLOCKS (BATCH / 2)                       // 8192 (2 samples/block)
#define COPY_CHUNKS  (NCLS * (FEAT / 4) / 4)           // 3,200,000 64B chunks
#define COPY_BLOCKS  ((COPY_CHUNKS + 255) / 256)       // 12500

// Scratch (allocation-free __device__ globals, zero-initialized at load).
// INVARIANT: g_counts is all-zero at kernel_launch entry. It is re-zeroed by
// dup_and_reset_kernel (the final launch) every call, so the invariant holds
// for the correctness run, the capture, and every graph replay alike.
__device__ int g_counts[NCLS];
__device__ int g_cnt_b[BATCH];      // per-sample class count, stashed by mega

__global__ void count_kernel(const int* __restrict__ targets) {
    int i = blockIdx.x * blockDim.x + threadIdx.x;
    if (i < BATCH) atomicAdd(&g_counts[targets[i]], 1);
}

// One grid doing both jobs so the DRAM pipe never drains:
//  - blocks [0, FUSED_BLOCKS): loss/tw + direct center rewrite (cnt==1)
//  - blocks [FUSED_BLOCKS, +COPY_BLOCKS): streaming copy of center rows,
//    skipping cnt==1 rows (owned by the fused half). cnt>1 rows ARE copied
//    (they are the accumulation base for dup_and_reset_kernel).
__global__ __launch_bounds__(256) void mega_kernel(
    const float4* __restrict__ inputs,
    const float4* __restrict__ centers,
    const float*  __restrict__ wpc,
    const int*    __restrict__ targets,
    float4* __restrict__ loss_out,
    float4* __restrict__ tw_out,
    float4* __restrict__ new_centers) {

    const int bid = blockIdx.x;

    if (bid < FUSED_BLOCKS) {
        // ---- fused half: 2 samples per block, 128 threads each ----
        const int group = threadIdx.x >> 7;         // 0..1
        const int d4    = threadIdx.x & 127;        // 0..127
        const int b = bid * 2 + group;

        const int t   = __ldg(&targets[b]);
        const int cnt = g_counts[t];
        const float w = LAMDA * __ldg(&wpc[t]);
        const float s = ALPHA / (1.0f + (float)cnt);

        if (d4 == 0) g_cnt_b[b] = cnt;   // stash for the dup pass

        const size_t ib = (size_t)b * (FEAT / 4) + d4;
        const size_t ic = (size_t)t * (FEAT / 4) + d4;
        const float4 x = inputs[ib];
        const float4 c = centers[ic];

        float4 l;
        float dx;
        dx = x.x - c.x; l.x = 0.5f * dx * dx;
        dx = x.y - c.y; l.y = 0.5f * dx * dx;
        dx = x.z - c.z; l.z = 0.5f * dx * dx;
        dx = x.w - c.w; l.w = 0.5f * dx * dx;

        loss_out[ib] = l;
        tw_out[ib]   = make_float4(w, w, w, w);

        if (cnt == 1) {
            // Sole sample of its class: full row rewrite, no atomics.
            new_centers[ic] = make_float4(c.x - s * x.x, c.y - s * x.y,
                                          c.z - s * x.z, c.w - s * x.w);
        }
        // cnt > 1: handled by dup_and_reset_kernel after the base row copy.
    } else {
        // ---- copy half: 64B (4 float4) per thread, one row per thread ----
        const int tchunk = (bid - FUSED_BLOCKS) * 256 + threadIdx.x;
        const size_t i = (size_t)tchunk * 4;        // float4 index
        const int row = (int)(i >> 7);              // 128 float4 per row
        if (row >= NCLS) return;
        if (g_counts[row] == 1) return;             // fused half owns it
        float4 v0 = __ldcs(&centers[i + 0]);
        float4 v1 = __ldcs(&centers[i + 1]);
        float4 v2 = __ldcs(&centers[i + 2]);
        float4 v3 = __ldcs(&centers[i + 3]);
        __stcs(&new_centers[i + 0], v0);
        __stcs(&new_centers[i + 1], v1);
        __stcs(&new_centers[i + 2], v2);
        __stcs(&new_centers[i + 3], v3);
    }
}

// Final pass: 128 blocks, each owning a contiguous 128-sample chunk.
// Phase 1: thread-parallel scan of the g_cnt_b stash (ONE load per thread,
//   not a serial walk) compacting duplicate-sample indices into smem.
// Phase 2: block processes its ~2-3 dup entries, 512 RED.F32 each onto the
//   copied base row.
// Also re-zeroes g_counts (safe: this kernel only reads g_cnt_b).
#define DUP_BLOCKS (BATCH / 128)    // 128
__global__ __launch_bounds__(128) void dup_and_reset_kernel(
    const float4* __restrict__ inputs,
    const int*    __restrict__ targets,
    float* __restrict__ new_centers) {

    __shared__ int s_list[128];
    __shared__ int s_n;

    const int tid = threadIdx.x;
    if (tid == 0) s_n = 0;
    __syncthreads();

    const int b = blockIdx.x * 128 + tid;
    const int mycnt = g_cnt_b[b];
    if (mycnt > 1) {
        int k = atomicAdd(&s_n, 1);
        s_list[k] = b;
    }
    __syncthreads();

    const int n = s_n;
    for (int e = 0; e < n; e++) {
        const int bb  = s_list[e];
        const int cnt = g_cnt_b[bb];
        const float s = ALPHA / (1.0f + (float)cnt);
        const int t   = __ldg(&targets[bb]);
        const float4 x = inputs[(size_t)bb * (FEAT / 4) + tid];
        float* dst = new_centers + (size_t)t * FEAT + tid * 4;
        atomicAdd(dst + 0, -s * x.x);
        atomicAdd(dst + 1, -s * x.y);
        atomicAdd(dst + 2, -s * x.z);
        atomicAdd(dst + 3, -s * x.w);
    }

    // Restore the all-zero invariant on g_counts (16384 threads, ~6 ints ea).
    const int g = blockIdx.x * 128 + tid;
    for (int i = g; i < NCLS; i += DUP_BLOCKS * 128) g_counts[i] = 0;
}

extern "C" void kernel_launch(void* const* d_in, const int* in_sizes, int n_in,
                              void* d_out, int out_size) {
    const float* inputs  = (const float*)d_in[0];   // [BATCH, FEAT]
    const float* centers = (const float*)d_in[1];   // [NCLS, FEAT]
    const float* wpc     = (const float*)d_in[2];   // [NCLS]
    const int*   targets = (const int*)d_in[3];     // [BATCH]

    float* out  = (float*)d_out;
    float* loss = out;                                  // [BATCH, FEAT]
    float* tw   = out + (size_t)BATCH * FEAT;           // [BATCH, FEAT]
    float* newc = out + (size_t)2 * BATCH * FEAT;       // [NCLS, FEAT]

    count_kernel<<<(BATCH + 255) / 256, 256>>>(targets);

    mega_kernel<<<FUSED_BLOCKS + COPY_BLOCKS, 256>>>(
        (const float4*)inputs, (const float4*)centers, wpc, targets,
        (float4*)loss, (float4*)tw, (float4*)newc);

    dup_and_reset_kernel<<<DUP_BLOCKS, 128>>>(
        (const float4*)inputs, targets, newc);
}

// round 14
// speedup vs baseline: 1.0986x; 1.0917x over previous
#include <cuda_runtime.h>
#include <cuda_bf16.h>

#define BATCH 16384
#define FEAT 512
#define NCLS 100000
#define ALPHA 0.5f
#define LAMDA 0.003f

#define FUSED_BLOCKS (BATCH / 2)                       // 8192 (2 samples/block)
#define COPY_CHUNKS  (NCLS * (FEAT / 4) / 4)           // 3,200,000 64B chunks
#define COPY_BLOCKS  ((COPY_CHUNKS + 255) / 256)       // 12500

// Scratch (allocation-free __device__ globals, zero-initialized at load).
// INVARIANT: g_counts and g_head are all-zero at kernel_launch entry; the
// final reset_kernel restores this every call (holds for correctness run,
// capture, and every replay). g_next needs no reset: every entry reachable
// from a head this call was written this call.
__device__ int g_counts[NCLS];
__device__ int g_head[NCLS];        // per-class list head, sample_idx+1 (0=end)
__device__ int g_next[BATCH];       // linked-list next, sample_idx+1 (0=end)

__global__ void count_kernel(const int* __restrict__ targets) {
    int i = blockIdx.x * blockDim.x + threadIdx.x;
    if (i < BATCH) {
        int t = targets[i];
        atomicAdd(&g_counts[t], 1);
        g_next[i] = atomicExch(&g_head[t], i + 1);
    }
}

// One grid, two jobs, DRAM never drains:
//  - blocks [0, FUSED_BLOCKS): loss/tw for all samples; direct center-row
//    rewrite for cnt==1 classes (c and x already in registers).
//  - blocks [FUSED_BLOCKS, +COPY_BLOCKS): center rows. Each WARP owns one
//    2KB row (32 threads x 64B). cnt==1 rows: skip (fused half owns them).
//    cnt==0: plain streaming copy. cnt>1 (~1.2% of rows): walk the class's
//    sample list (warp-uniform, ~2 iters), write c - s*sum(x) directly —
//    no atomics, no post-pass.
__global__ __launch_bounds__(256) void mega_kernel(
    const float4* __restrict__ inputs,
    const float4* __restrict__ centers,
    const float*  __restrict__ wpc,
    const int*    __restrict__ targets,
    float4* __restrict__ loss_out,
    float4* __restrict__ tw_out,
    float4* __restrict__ new_centers) {

    const int bid = blockIdx.x;

    if (bid < FUSED_BLOCKS) {
        // ---- fused half: 2 samples per block, 128 threads each ----
        const int group = threadIdx.x >> 7;         // 0..1
        const int d4    = threadIdx.x & 127;        // 0..127
        const int b = bid * 2 + group;

        const int t   = __ldg(&targets[b]);
        const int cnt = g_counts[t];
        const float w = LAMDA * __ldg(&wpc[t]);
        const float s = ALPHA / (1.0f + (float)cnt);

        const size_t ib = (size_t)b * (FEAT / 4) + d4;
        const size_t ic = (size_t)t * (FEAT / 4) + d4;
        const float4 x = inputs[ib];
        const float4 c = centers[ic];

        float4 l;
        float dx;
        dx = x.x - c.x; l.x = 0.5f * dx * dx;
        dx = x.y - c.y; l.y = 0.5f * dx * dx;
        dx = x.z - c.z; l.z = 0.5f * dx * dx;
        dx = x.w - c.w; l.w = 0.5f * dx * dx;

        loss_out[ib] = l;
        tw_out[ib]   = make_float4(w, w, w, w);

        if (cnt == 1) {
            new_centers[ic] = make_float4(c.x - s * x.x, c.y - s * x.y,
                                          c.z - s * x.z, c.w - s * x.w);
        }
        // cnt > 1: finalized by the copy half via the class list.
    } else {
        // ---- copy half: 64B (4 float4) per thread, warp == one row ----
        const int tchunk = (bid - FUSED_BLOCKS) * 256 + threadIdx.x;
        const size_t i = (size_t)tchunk * 4;        // float4 index
        const int row = (int)(i >> 7);              // 128 float4 per row
        if (row >= NCLS) return;
        const int cnt = g_counts[row];
        if (cnt == 1) return;                       // fused half owns it

        float4 c0 = __ldcs(&centers[i + 0]);
        float4 c1 = __ldcs(&centers[i + 1]);
        float4 c2 = __ldcs(&centers[i + 2]);
        float4 c3 = __ldcs(&centers[i + 3]);

        if (cnt > 1) {
            // Warp-uniform list walk: sum inputs of this class's samples.
            const int col = (int)(i & 127);         // float4 offset in row
            float4 a0 = make_float4(0.f, 0.f, 0.f, 0.f);
            float4 a1 = a0, a2 = a0, a3 = a0;
            int h = g_head[row];
            while (h) {
                const int b = h - 1;
                const float4* xr = inputs + (size_t)b * (FEAT / 4) + col;
                float4 x0 = __ldcs(&xr[0]);
                float4 x1 = __ldcs(&xr[1]);
                float4 x2 = __ldcs(&xr[2]);
                float4 x3 = __ldcs(&xr[3]);
                a0.x += x0.x; a0.y += x0.y; a0.z += x0.z; a0.w += x0.w;
                a1.x += x1.x; a1.y += x1.y; a1.z += x1.z; a1.w += x1.w;
                a2.x += x2.x; a2.y += x2.y; a2.z += x2.z; a2.w += x2.w;
                a3.x += x3.x; a3.y += x3.y; a3.z += x3.z; a3.w += x3.w;
                h = g_next[b];
            }
            const float s = ALPHA / (1.0f + (float)cnt);
            c0.x -= s * a0.x; c0.y -= s * a0.y; c0.z -= s * a0.z; c0.w -= s * a0.w;
            c1.x -= s * a1.x; c1.y -= s * a1.y; c1.z -= s * a1.z; c1.w -= s * a1.w;
            c2.x -= s * a2.x; c2.y -= s * a2.y; c2.z -= s * a2.z; c2.w -= s * a2.w;
            c3.x -= s * a3.x; c3.y -= s * a3.y; c3.z -= s * a3.z; c3.w -= s * a3.w;
        }
        __stcs(&new_centers[i + 0], c0);
        __stcs(&new_centers[i + 1], c1);
        __stcs(&new_centers[i + 2], c2);
        __stcs(&new_centers[i + 3], c3);
    }
}

// Restore the all-zero invariant on g_counts and g_head.
__global__ __launch_bounds__(256) void reset_kernel() {
    const int i = blockIdx.x * blockDim.x + threadIdx.x;
    if (i < NCLS) { g_counts[i] = 0; g_head[i] = 0; }
}

extern "C" void kernel_launch(void* const* d_in, const int* in_sizes, int n_in,
                              void* d_out, int out_size) {
    const float* inputs  = (const float*)d_in[0];   // [BATCH, FEAT]
    const float* centers = (const float*)d_in[1];   // [NCLS, FEAT]
    const float* wpc     = (const float*)d_in[2];   // [NCLS]
    const int*   targets = (const int*)d_in[3];     // [BATCH]

    float* out  = (float*)d_out;
    float* loss = out;                                  // [BATCH, FEAT]
    float* tw   = out + (size_t)BATCH * FEAT;           // [BATCH, FEAT]
    float* newc = out + (size_t)2 * BATCH * FEAT;       // [NCLS, FEAT]

    count_kernel<<<(BATCH + 255) / 256, 256>>>(targets);

    mega_kernel<<<FUSED_BLOCKS + COPY_BLOCKS, 256>>>(
        (const float4*)inputs, (const float4*)centers, wpc, targets,
        (float4*)loss, (float4*)tw, (float4*)newc);

    reset_kernel<<<(NCLS + 255) / 256, 256>>>();
}